// round 12
// baseline (speedup 1.0000x reference)
#include <cuda_runtime.h>
#include <cuda_fp16.h>

#define NBATCH 4
#define CCH 256
#define FH 100
#define FW 152
#define HW (FH*FW)           // 15200
#define FWC (FW*CCH)         // 38912  (element stride)
#define NROI 4000
#define OUT_PER_ROI (CCH*49)       // 12544 floats, linear
#define SMEM_BYTES (OUT_PER_ROI*2) // 25088 B (fp16 stage)

// NHWC scratch in fp16 (31MB). Math stays fp32; storage is half.
__device__ __half g_nhwc_h[NBATCH * HW * CCH];

// ---------------------------------------------------------------------------
// Kernel A: NCHW(f32) -> NHWC(fp16) transpose. 128ch x 32hw tiles, 3800
// blocks, 16 independent LDGs/thread. ~13us measured (near DRAM floor).
// ---------------------------------------------------------------------------
__global__ __launch_bounds__(256) void transpose_kernel(const float* __restrict__ in) {
    __shared__ float tile[128][33];
    const int b   = blockIdx.z;
    const int hw0 = blockIdx.x * 32;
    const int c0  = blockIdx.y * 128;
    const int x   = threadIdx.x;
    const int y   = threadIdx.y;

    const float* src = in + (size_t)b * CCH * HW + (size_t)(c0 + y) * HW + hw0 + x;
    #pragma unroll
    for (int k = 0; k < 16; k++)
        tile[y + 8*k][x] = __ldcs(src + (size_t)(8*k) * HW);
    __syncthreads();

    __half* dst = g_nhwc_h + (size_t)b * HW * CCH + (size_t)hw0 * CCH + c0 + x;
    #pragma unroll
    for (int k = 0; k < 4; k++) {
        const int hw = y + 8*k;
        #pragma unroll
        for (int m = 0; m < 4; m++)
            dst[(size_t)hw * CCH + 32*m] = __float2half_rn(tile[x + 32*m][hw]);
    }
}

// ---------------------------------------------------------------------------
// Row-group body: half2 gathers (2 consecutive channels per 32-bit LDG),
// fp32 lerp math, horizontal pair-sum rolling carry; pooled results stored
// to the fp16 smem stage.
// ---------------------------------------------------------------------------
template<int NR>
__device__ __forceinline__ void process_rows_h2(
    int i0, const __half* __restrict__ fbase, int c0,
    const int* s_ws, const int* s_hs,
    const float* s_wf, const float* s_hf,
    const float* s_wm, const float* s_hm,
    __half* s_out)
{
    float2 hprev[7];
    #pragma unroll
    for (int k = 0; k < NR; ++k) {
        const int i = i0 + k;
        const __half* r0 = fbase + s_hs[i] * FWC;
        const float hf = s_hf[i];
        const float hm = s_hm[i];

        float2 cur[8];
        #pragma unroll
        for (int j = 0; j < 8; j++) {
            const int w0 = s_ws[j];
            float2 a00 = __half22float2(*(const half2*)(r0 + w0));
            float2 a01 = __half22float2(*(const half2*)(r0 + w0 + CCH));
            float2 a10 = __half22float2(*(const half2*)(r0 + w0 + FWC));
            float2 a11 = __half22float2(*(const half2*)(r0 + w0 + FWC + CCH));
            float wf = s_wf[j];
            float m  = hm * s_wm[j];
            float tx = a00.x + (a01.x - a00.x) * wf;
            float ty = a00.y + (a01.y - a00.y) * wf;
            float bx = a10.x + (a11.x - a10.x) * wf;
            float by = a10.y + (a11.y - a10.y) * wf;
            cur[j].x = (tx + (bx - tx) * hf) * m;
            cur[j].y = (ty + (by - ty) * hf) * m;
        }

        float2 hcur[7];
        #pragma unroll
        for (int j = 0; j < 7; j++) {
            hcur[j].x = cur[j].x + cur[j+1].x;
            hcur[j].y = cur[j].y + cur[j+1].y;
        }

        if (k > 0) {
            int rb = (i - 1) * 7;
            #pragma unroll
            for (int j = 0; j < 7; j++) {
                s_out[c0 * 49 + rb + j] =
                    __float2half_rn(0.25f * (hprev[j].x + hcur[j].x));
                s_out[(c0 + 1) * 49 + rb + j] =
                    __float2half_rn(0.25f * (hprev[j].y + hcur[j].y));
            }
        }
        #pragma unroll
        for (int j = 0; j < 7; j++) hprev[j] = hcur[j];
    }
}

// ---------------------------------------------------------------------------
// Kernel B: one 256-thread block per roi. 128 half2-threads (=256 channels)
// x 2 row-groups, proven 5+4 split, fp16 smem stage.
// ONLY change vs round 11: launch_bounds(256,6) -> 42-reg target ->
// 6 CTAs/SM = 48 warps (+20% over round 11's 40). half2's in-flight data
// cost (1 reg per corner-pair) makes the squeeze survivable where the
// scalar version's wasn't (round 5).
// ---------------------------------------------------------------------------
__global__ __launch_bounds__(256, 6) void roi_kernel(
    const float* __restrict__ rois,
    const int*   __restrict__ bids,
    float*       __restrict__ out)
{
    extern __shared__ __half s_out[];   // [256][49] fp16
    __shared__ int   s_ws[8], s_hs[8];
    __shared__ float s_wf[8], s_hf[8], s_wm[8], s_hm[8];

    const int r = blockIdx.x;
    const int t = threadIdx.x;
    const int p = t & 127;             // channel-pair index (channels 2p, 2p+1)
    const int g = t >> 7;              // warps 0-3: g=0, warps 4-7: g=1

    if (t < 8) {
        float x1 = rois[r*4 + 0] * 0.0625f;
        float x2 = rois[r*4 + 2] * 0.0625f;
        float bw = fmaxf(x2 - x1 + 1.0f, 0.0f) * (1.0f / 7.0f);
        float w  = x1 + (float)t * bw;
        s_wm[t]  = (w >= 0.0f && w < (float)FW) ? 1.0f : 0.0f;
        float wsf = fminf(fmaxf(floorf(w), 0.0f), (float)(FW - 2));
        s_ws[t]  = (int)wsf * CCH;     // pre-scaled column offset (elements)
        s_wf[t]  = w - wsf;
    } else if (t < 16) {
        int i = t & 7;
        float y1 = rois[r*4 + 1] * 0.0625f;
        float y2 = rois[r*4 + 3] * 0.0625f;
        float bh = fmaxf(y2 - y1 + 1.0f, 0.0f) * (1.0f / 7.0f);
        float h  = y1 + (float)i * bh;
        s_hm[i]  = (h >= 0.0f && h < (float)FH) ? 1.0f : 0.0f;
        float hsf = fminf(fmaxf(floorf(h), 0.0f), (float)(FH - 2));
        s_hs[i]  = (int)hsf;
        s_hf[i]  = h - hsf;
    }
    __syncthreads();

    const int b = bids[r];
    const __half* fbase = g_nhwc_h + (size_t)b * HW * CCH + 2 * p;

    if (g == 0)
        process_rows_h2<5>(0, fbase, 2*p, s_ws, s_hs, s_wf, s_hf, s_wm, s_hm, s_out);
    else
        process_rows_h2<4>(4, fbase, 2*p, s_ws, s_hs, s_wf, s_hf, s_wm, s_hm, s_out);

    __syncthreads();

    // Coalesced flush: 4 halfs (8B-aligned) -> float4 store.
    float4* op = (float4*)(out + (size_t)r * OUT_PER_ROI);
    #pragma unroll
    for (int m = t; m < OUT_PER_ROI / 4; m += 256) {
        const half2* hp = (const half2*)(s_out + 4 * m);
        float2 lo = __half22float2(hp[0]);
        float2 hi = __half22float2(hp[1]);
        op[m] = make_float4(lo.x, lo.y, hi.x, hi.y);
    }
}

// ---------------------------------------------------------------------------
extern "C" void kernel_launch(void* const* d_in, const int* in_sizes, int n_in,
                              void* d_out, int out_size) {
    const float* features = (const float*)d_in[0];
    const float* rois     = (const float*)d_in[1];
    const int*   bids     = (const int*)d_in[2];
    float*       out      = (float*)d_out;

    dim3 tgrid(HW / 32, CCH / 128, NBATCH);   // (475, 2, 4) = 3800 blocks
    transpose_kernel<<<tgrid, dim3(32, 8)>>>(features);

    cudaFuncSetAttribute(roi_kernel,
                         cudaFuncAttributeMaxDynamicSharedMemorySize,
                         SMEM_BYTES);
    roi_kernel<<<NROI, 256, SMEM_BYTES>>>(rois, bids, out);
}

// round 13
// speedup vs baseline: 1.2114x; 1.2114x over previous
#include <cuda_runtime.h>
#include <cuda_fp16.h>

#define NBATCH 4
#define CCH 256
#define FH 100
#define FW 152
#define HW (FH*FW)           // 15200
#define FWC (FW*CCH)         // 38912  (element stride)
#define NROI 4000
#define OUT_PER_ROI (CCH*49)       // 12544 floats, linear
#define SMEM_BYTES (OUT_PER_ROI*2) // 25088 B (fp16 stage)

// NHWC scratch in fp16 (31MB). Math stays fp32; storage is half.
__device__ __half g_nhwc_h[NBATCH * HW * CCH];

// ---------------------------------------------------------------------------
// Kernel A: NCHW(f32) -> NHWC(fp16) transpose. 128ch x 32hw tiles, 3800
// blocks, 16 independent LDGs/thread. ~13us measured (near DRAM floor).
// ---------------------------------------------------------------------------
__global__ __launch_bounds__(256) void transpose_kernel(const float* __restrict__ in) {
    __shared__ float tile[128][33];
    const int b   = blockIdx.z;
    const int hw0 = blockIdx.x * 32;
    const int c0  = blockIdx.y * 128;
    const int x   = threadIdx.x;
    const int y   = threadIdx.y;

    const float* src = in + (size_t)b * CCH * HW + (size_t)(c0 + y) * HW + hw0 + x;
    #pragma unroll
    for (int k = 0; k < 16; k++)
        tile[y + 8*k][x] = __ldcs(src + (size_t)(8*k) * HW);
    __syncthreads();

    __half* dst = g_nhwc_h + (size_t)b * HW * CCH + (size_t)hw0 * CCH + c0 + x;
    #pragma unroll
    for (int k = 0; k < 4; k++) {
        const int hw = y + 8*k;
        #pragma unroll
        for (int m = 0; m < 4; m++)
            dst[(size_t)hw * CCH + 32*m] = __float2half_rn(tile[x + 32*m][hw]);
    }
}

// ---------------------------------------------------------------------------
// Row-group body: half2 gathers, 4-weight dot product per sample (weights
// from the per-roi LUT with mask and 0.25 pool factor folded in), pair-sum
// rolling carry, fp16 smem stage.
// ---------------------------------------------------------------------------
template<int NR>
__device__ __forceinline__ void process_rows_h2(
    int i0, const __half* __restrict__ fbase, int c0,
    const int* s_ws, const int* s_hs,
    const float (*s_w4)[8][4],
    __half* s_out)
{
    float2 hprev[7];
    #pragma unroll
    for (int k = 0; k < NR; ++k) {
        const int i = i0 + k;
        const __half* r0 = fbase + s_hs[i] * FWC;
        const float (*wrow)[4] = s_w4[i];

        float2 cur[8];
        #pragma unroll
        for (int j = 0; j < 8; j++) {
            const int w0 = s_ws[j];
            float2 a00 = __half22float2(*(const half2*)(r0 + w0));
            float2 a01 = __half22float2(*(const half2*)(r0 + w0 + CCH));
            float2 a10 = __half22float2(*(const half2*)(r0 + w0 + FWC));
            float2 a11 = __half22float2(*(const half2*)(r0 + w0 + FWC + CCH));
            float q0 = wrow[j][0], q1 = wrow[j][1];
            float q2 = wrow[j][2], q3 = wrow[j][3];
            cur[j].x = fmaf(a11.x, q3, fmaf(a10.x, q2, fmaf(a01.x, q1, a00.x * q0)));
            cur[j].y = fmaf(a11.y, q3, fmaf(a10.y, q2, fmaf(a01.y, q1, a00.y * q0)));
        }

        float2 hcur[7];
        #pragma unroll
        for (int j = 0; j < 7; j++) {
            hcur[j].x = cur[j].x + cur[j+1].x;
            hcur[j].y = cur[j].y + cur[j+1].y;
        }

        if (k > 0) {
            int rb = (i - 1) * 7;
            #pragma unroll
            for (int j = 0; j < 7; j++) {
                // 0.25 already folded into the weights
                s_out[c0 * 49 + rb + j]       = __float2half_rn(hprev[j].x + hcur[j].x);
                s_out[(c0 + 1) * 49 + rb + j] = __float2half_rn(hprev[j].y + hcur[j].y);
            }
        }
        #pragma unroll
        for (int j = 0; j < 7; j++) hprev[j] = hcur[j];
    }
}

// ---------------------------------------------------------------------------
// Kernel B: one 256-thread block per roi. 128 half2-threads x 2 row-groups,
// proven 5+4 split, fp16 smem stage, (256,5) = 48 regs / 40 warps (the
// measured optimum; 40-42 regs spills — R12). NEW vs round 11: per-roi
// 4-weight LUT (mask + 0.25 folded) replaces the lerp chain: fewer issue
// slots and 16 fewer hoisted registers in the mainloop.
// ---------------------------------------------------------------------------
__global__ __launch_bounds__(256, 5) void roi_kernel(
    const float* __restrict__ rois,
    const int*   __restrict__ bids,
    float*       __restrict__ out)
{
    extern __shared__ __half s_out[];   // [256][49] fp16
    __shared__ float s_w4[8][8][4];     // [i][j][w00,w01,w10,w11], 1KB
    __shared__ int   s_ws[8], s_hs[8];

    const int r = blockIdx.x;
    const int t = threadIdx.x;
    const int p = t & 127;             // channel-pair index (channels 2p, 2p+1)
    const int g = t >> 7;              // warps 0-3: g=0, warps 4-7: g=1

    if (t < 64) {
        const int i = t >> 3;          // h-sample index
        const int j = t & 7;           // w-sample index
        float x1 = rois[r*4 + 0] * 0.0625f;
        float x2 = rois[r*4 + 2] * 0.0625f;
        float y1 = rois[r*4 + 1] * 0.0625f;
        float y2 = rois[r*4 + 3] * 0.0625f;
        float bw = fmaxf(x2 - x1 + 1.0f, 0.0f) * (1.0f / 7.0f);
        float bh = fmaxf(y2 - y1 + 1.0f, 0.0f) * (1.0f / 7.0f);
        float w  = x1 + (float)j * bw;
        float h  = y1 + (float)i * bh;
        float wm = (w >= 0.0f && w < (float)FW) ? 1.0f : 0.0f;
        float hm = (h >= 0.0f && h < (float)FH) ? 1.0f : 0.0f;
        float wsf = fminf(fmaxf(floorf(w), 0.0f), (float)(FW - 2));
        float hsf = fminf(fmaxf(floorf(h), 0.0f), (float)(FH - 2));
        float wf = w - wsf;
        float hf = h - hsf;
        float m  = hm * wm * 0.25f;            // mask + pool factor folded
        s_w4[i][j][0] = (1.0f - hf) * (1.0f - wf) * m;
        s_w4[i][j][1] = (1.0f - hf) * wf * m;
        s_w4[i][j][2] = hf * (1.0f - wf) * m;
        s_w4[i][j][3] = hf * wf * m;
        if (i == 0) s_ws[j] = (int)wsf * CCH;  // pre-scaled column offset
        if (j == 0) s_hs[i] = (int)hsf;
    }
    __syncthreads();

    const int b = bids[r];
    const __half* fbase = g_nhwc_h + (size_t)b * HW * CCH + 2 * p;

    if (g == 0)
        process_rows_h2<5>(0, fbase, 2*p, s_ws, s_hs, s_w4, s_out);
    else
        process_rows_h2<4>(4, fbase, 2*p, s_ws, s_hs, s_w4, s_out);

    __syncthreads();

    // Coalesced flush: 4 halfs (8B-aligned) -> float4 store.
    float4* op = (float4*)(out + (size_t)r * OUT_PER_ROI);
    #pragma unroll
    for (int m = t; m < OUT_PER_ROI / 4; m += 256) {
        const half2* hp = (const half2*)(s_out + 4 * m);
        float2 lo = __half22float2(hp[0]);
        float2 hi = __half22float2(hp[1]);
        op[m] = make_float4(lo.x, lo.y, hi.x, hi.y);
    }
}

// ---------------------------------------------------------------------------
extern "C" void kernel_launch(void* const* d_in, const int* in_sizes, int n_in,
                              void* d_out, int out_size) {
    const float* features = (const float*)d_in[0];
    const float* rois     = (const float*)d_in[1];
    const int*   bids     = (const int*)d_in[2];
    float*       out      = (float*)d_out;

    dim3 tgrid(HW / 32, CCH / 128, NBATCH);   // (475, 2, 4) = 3800 blocks
    transpose_kernel<<<tgrid, dim3(32, 8)>>>(features);

    cudaFuncSetAttribute(roi_kernel,
                         cudaFuncAttributeMaxDynamicSharedMemorySize,
                         SMEM_BYTES);
    roi_kernel<<<NROI, 256, SMEM_BYTES>>>(rois, bids, out);
}